// round 12
// baseline (speedup 1.0000x reference)
#include <cuda_runtime.h>
#include <cuda_fp16.h>
#include <cstdint>

#define DM    1024
#define NH    16
#define HD    64
#define BATCH 2
#define SEQ   2048
#define MTOT  (BATCH*SEQ)   // 4096

// Scratch (allocation-free rule: __device__ globals)
__device__ __half g_qh [(long long)BATCH*NH*SEQ*HD];  // [b,h,s,hd]
__device__ __half g_kh [(long long)BATCH*NH*SEQ*HD];  // [b,h,s,hd]
__device__ __half g_vt [(long long)BATCH*NH*HD*SEQ];  // [b,h,hd,s]  (transposed!)
__device__ __half g_aoh[(long long)MTOT*DM];          // [b*s, d]
__device__ __half g_xh [(long long)MTOT*DM];          // x as fp16
__device__ __half g_WhT[(long long)4*DM*DM];          // W^T: [w][n][k]

__device__ __forceinline__ uint32_t smem_u32(const void* p) {
    uint32_t a;
    asm("{ .reg .u64 t; cvta.to.shared.u64 t, %1; cvt.u32.u64 %0, t; }"
        : "=r"(a) : "l"(p));
    return a;
}

__device__ __forceinline__ void cp16(uint32_t dst, const void* src) {
    asm volatile("cp.async.cg.shared.global [%0], [%1], 16;"
                 :: "r"(dst), "l"(src) : "memory");
}
#define CP_COMMIT() asm volatile("cp.async.commit_group;" ::: "memory")
#define CP_WAIT(n)  asm volatile("cp.async.wait_group %0;" :: "n"(n) : "memory")

__device__ __forceinline__ void mma_f16(float c[4], uint32_t a0, uint32_t a1,
                                        uint32_t a2, uint32_t a3,
                                        uint32_t b0, uint32_t b1) {
    asm volatile(
        "mma.sync.aligned.m16n8k16.row.col.f32.f16.f16.f32 "
        "{%0,%1,%2,%3}, {%4,%5,%6,%7}, {%8,%9}, {%0,%1,%2,%3};"
        : "+f"(c[0]), "+f"(c[1]), "+f"(c[2]), "+f"(c[3])
        : "r"(a0), "r"(a1), "r"(a2), "r"(a3), "r"(b0), "r"(b1));
}

// ===========================================================================
// Prep 1: x -> fp16.   Prep 2: W -> fp16 transposed [n][k].
// ===========================================================================
__global__ void __launch_bounds__(256)
prep_x(const float* __restrict__ x)
{
    const int i = blockIdx.x * blockDim.x + threadIdx.x;
    float4 v = ((const float4*)x)[i];
    ((__half2*)g_xh)[i * 2 + 0] = __floats2half2_rn(v.x, v.y);
    ((__half2*)g_xh)[i * 2 + 1] = __floats2half2_rn(v.z, v.w);
}

__global__ void __launch_bounds__(256)
prep_wt(const float* __restrict__ wq, const float* __restrict__ wk,
        const float* __restrict__ wv, const float* __restrict__ wo)
{
    __shared__ float s[32][33];
    const int w = blockIdx.z;
    const float* W = (w == 0) ? wq : (w == 1) ? wk : (w == 2) ? wv : wo;
    const int n0 = blockIdx.x * 32, k0 = blockIdx.y * 32;
    const int tx = threadIdx.x & 31, ty = threadIdx.x >> 5;   // 32 x 8
    #pragma unroll
    for (int r = 0; r < 4; r++)
        s[ty + r * 8][tx] = W[(size_t)(k0 + ty + r * 8) * DM + n0 + tx];
    __syncthreads();
    #pragma unroll
    for (int r = 0; r < 4; r++)
        g_WhT[(size_t)w * DM * DM + (size_t)(n0 + ty + r * 8) * DM + k0 + tx] =
            __float2half_rn(s[tx][ty + r * 8]);
}

// ===========================================================================
// FP16 mma.sync GEMM (unchanged from R11 — passing)
// ===========================================================================
#define APITCH 56
#define ATILEH (128*APITCH)
#define BUFH   (2*ATILEH)
#define NSTAGE 3
#define GEMM_SMEM_BYTES (NSTAGE*BUFH*2)   // 86016
#define NKT (DM/32)

template<int MODE>
__global__ void __launch_bounds__(256, 2)
gemm_mma(const float* __restrict__ b0,
         const float* __restrict__ b1,
         const float* __restrict__ b2,
         float* __restrict__ Cout)
{
    extern __shared__ __half smh[];
    const uint32_t sb = smem_u32(smh);

    const int t   = threadIdx.x;
    const int wid = t >> 5, lane = t & 31;
    const int grp = lane >> 2, qid = lane & 3;
    const int wr  = wid & 1, wc = wid >> 1;
    const int bn  = blockIdx.x * 128, bm = blockIdx.y * 128;
    const int z   = (MODE == 3) ? 3 : blockIdx.z;

    const __half* Ap = (MODE == 3) ? g_aoh : g_xh;
    const __half* Wt = g_WhT + (size_t)z * DM * DM;
    const float* bias = (MODE == 3) ? b0 : (z == 0) ? b0 : (z == 1) ? b1 : b2;

    float c[4][4][4];
    #pragma unroll
    for (int mt = 0; mt < 4; mt++)
        #pragma unroll
        for (int nt = 0; nt < 4; nt++)
            #pragma unroll
            for (int i = 0; i < 4; i++) c[mt][nt][i] = 0.f;

    auto loadA = [&](int p, int kt) {
        #pragma unroll
        for (int i = 0; i < 2; i++) {
            int idx = t + 256 * i;
            int row = idx >> 2, c4 = idx & 3;
            cp16(sb + (uint32_t)(p * BUFH + row * APITCH + c4 * 8) * 2,
                 &Ap[(size_t)(bm + row) * DM + kt * 32 + c4 * 8]);
        }
    };
    auto loadW = [&](int p, int kt) {
        #pragma unroll
        for (int i = 0; i < 2; i++) {
            int idx = t + 256 * i;
            int row = idx >> 2, c4 = idx & 3;
            cp16(sb + (uint32_t)(p * BUFH + ATILEH + row * APITCH + c4 * 8) * 2,
                 &Wt[(size_t)(bn + row) * DM + kt * 32 + c4 * 8]);
        }
    };

    loadA(0, 0); loadW(0, 0); CP_COMMIT();
    loadA(1, 1); loadW(1, 1); CP_COMMIT();

    int cs = 0, ls = 2;
    for (int kt = 0; kt < NKT; kt++) {
        if (kt + 1 < NKT) { CP_WAIT(1); } else { CP_WAIT(0); }
        __syncthreads();

        if (kt + 2 < NKT) {
            loadA(ls, kt + 2); loadW(ls, kt + 2); CP_COMMIT();
            ls = (ls + 1 == NSTAGE) ? 0 : ls + 1;
        }

        const __half* As = smh + cs * BUFH;
        const __half* Ws = smh + cs * BUFH + ATILEH;
        #pragma unroll
        for (int ks = 0; ks < 2; ks++) {
            const int kh = ks * 16;
            uint32_t af[4][4];
            #pragma unroll
            for (int mt = 0; mt < 4; mt++) {
                const __half* ab = As + (wr * 64 + mt * 16 + grp) * APITCH + kh + 2 * qid;
                af[mt][0] = *(const uint32_t*)(ab);
                af[mt][1] = *(const uint32_t*)(ab + 8 * APITCH);
                af[mt][2] = *(const uint32_t*)(ab + 8);
                af[mt][3] = *(const uint32_t*)(ab + 8 * APITCH + 8);
            }
            uint32_t bf[4][2];
            #pragma unroll
            for (int nt = 0; nt < 4; nt++) {
                const __half* bb = Ws + (wc * 32 + nt * 8 + grp) * APITCH + kh + 2 * qid;
                bf[nt][0] = *(const uint32_t*)(bb);
                bf[nt][1] = *(const uint32_t*)(bb + 8);
            }
            #pragma unroll
            for (int mt = 0; mt < 4; mt++)
                #pragma unroll
                for (int nt = 0; nt < 4; nt++)
                    mma_f16(c[mt][nt], af[mt][0], af[mt][1], af[mt][2], af[mt][3],
                            bf[nt][0], bf[nt][1]);
        }
        cs = (cs + 1 == NSTAGE) ? 0 : cs + 1;
    }

    #pragma unroll
    for (int mt = 0; mt < 4; mt++) {
        #pragma unroll
        for (int nt = 0; nt < 4; nt++) {
            const int gc = bn + wc * 32 + nt * 8 + 2 * qid;
            const float bx = bias[gc], by = bias[gc + 1];
            #pragma unroll
            for (int half = 0; half < 2; half++) {
                const int gr = bm + wr * 64 + mt * 16 + grp + half * 8;
                const float vx = c[mt][nt][half * 2 + 0] + bx;
                const float vy = c[mt][nt][half * 2 + 1] + by;
                if (MODE == 3) {
                    float2 v; v.x = vx; v.y = vy;
                    *(float2*)&Cout[(size_t)gr * DM + gc] = v;
                } else {
                    const int b = gr >> 11, s = gr & (SEQ - 1);
                    const int h = gc >> 6,  hd = gc & (HD - 1);
                    if (z == 0) {
                        *(__half2*)&g_qh[((size_t)((b * NH + h) * SEQ + s)) * HD + hd] =
                            __floats2half2_rn(vx, vy);
                    } else if (z == 1) {
                        *(__half2*)&g_kh[((size_t)((b * NH + h) * SEQ + s)) * HD + hd] =
                            __floats2half2_rn(vx, vy);
                    } else {
                        __half* vtp = g_vt + ((size_t)(b * NH + h) * HD) * SEQ;
                        vtp[(size_t)(hd + 0) * SEQ + s] = __float2half_rn(vx);
                        vtp[(size_t)(hd + 1) * SEQ + s] = __float2half_rn(vy);
                    }
                }
            }
        }
    }
}

// ===========================================================================
// FP16 mma.sync flash attention.  BQ=128, BK=64, 256 threads = 8 warps
// (warp w owns Q-rows [w*16, w*16+16)).  2-stage cp.async K/V(transposed).
// grid: (SEQ/128, BATCH*NH), reversed qt.  Causal: ntiles = 2*qt+2 k-tiles;
// mask applied on the last two tiles only.
// ===========================================================================
#define QP 72                         // half pitch: 144 B (16-mult, conflict-free)
#define SMQ   0                       // 128 rows: 128*72 = 9216 halves
#define SMKV  (128*QP)                // 9216
#define KVH   (2*64*QP)               // 9216 halves per stage (K + Vt)
#define SMP   (SMKV + 2*KVH)          // 27648
#define ATTN_H (SMP + 8*16*QP)        // 36864 halves
#define ATTN_SMEM_BYTES (ATTN_H*2)    // 73728

__global__ void __launch_bounds__(256)
attn_mma()
{
    extern __shared__ __half smh[];
    const uint32_t sb = smem_u32(smh);

    const int t    = threadIdx.x;
    const int wid  = t >> 5, lane = t & 31;
    const int grp  = lane >> 2, qid = lane & 3;
    const int qt   = gridDim.x - 1 - blockIdx.x;
    const int bh   = blockIdx.y;
    const int q0   = qt * 128;

    const __half* Qg  = g_qh + ((size_t)bh * SEQ + q0) * HD;
    const __half* Kg  = g_kh + (size_t)bh * SEQ * HD;
    const __half* Vtg = g_vt + (size_t)bh * HD * SEQ;

    auto loadKV = [&](int p, int kt) {
        const int k0 = kt * 64;
        const uint32_t kb = sb + (uint32_t)(SMKV + p * KVH) * 2;
        #pragma unroll
        for (int i = 0; i < 2; i++) {
            int idx = t + 256 * i;
            int row = idx >> 3, c8 = idx & 7;       // K: 64 rows x 8 chunks
            cp16(kb + (uint32_t)(row * QP + c8 * 8) * 2,
                 &Kg[(size_t)(k0 + row) * HD + c8 * 8]);
        }
        #pragma unroll
        for (int i = 0; i < 2; i++) {
            int idx = t + 256 * i;
            int d = idx >> 3, c8 = idx & 7;         // Vt: 64 d-rows x 8 s-chunks
            cp16(kb + (uint32_t)(64 * QP + d * QP + c8 * 8) * 2,
                 &Vtg[(size_t)d * SEQ + k0 + c8 * 8]);
        }
    };

    // Q tile (128 rows) + first K/V stage
    #pragma unroll
    for (int i = 0; i < 4; i++) {
        int idx = t + 256 * i;
        int row = idx >> 3, c8 = idx & 7;
        cp16(sb + (uint32_t)(SMQ + row * QP + c8 * 8) * 2,
             &Qg[(size_t)row * HD + c8 * 8]);
    }
    loadKV(0, 0);
    CP_COMMIT();

    float o[8][4];
    #pragma unroll
    for (int nt = 0; nt < 8; nt++)
        #pragma unroll
        for (int i = 0; i < 4; i++) o[nt][i] = 0.f;
    float m0 = -1e30f, m1 = -1e30f, l0 = 0.f, l1 = 0.f;

    __half* Pw = smh + SMP + wid * 16 * QP;

    const int ntiles = 2 * qt + 2;
    for (int kt = 0; kt < ntiles; kt++) {
        const int p = kt & 1;
        if (kt + 1 < ntiles) {
            loadKV(p ^ 1, kt + 1); CP_COMMIT();
            CP_WAIT(1);
        } else {
            CP_WAIT(0);
        }
        __syncthreads();

        const int k0 = kt * 64;
        const __half* Ks = smh + SMKV + p * KVH;
        const __half* Vs = Ks + 64 * QP;

        // ---- S = Q @ K^T ----
        float s[8][4];
        #pragma unroll
        for (int nt = 0; nt < 8; nt++)
            #pragma unroll
            for (int i = 0; i < 4; i++) s[nt][i] = 0.f;

        const __half* Qs = smh + SMQ + (wid * 16) * QP;
        #pragma unroll
        for (int ks = 0; ks < 4; ks++) {
            const int kh = ks * 16;
            const __half* ab = Qs + grp * QP + kh + 2 * qid;
            uint32_t a0 = *(const uint32_t*)(ab);
            uint32_t a1 = *(const uint32_t*)(ab + 8 * QP);
            uint32_t a2 = *(const uint32_t*)(ab + 8);
            uint32_t a3 = *(const uint32_t*)(ab + 8 * QP + 8);
            #pragma unroll
            for (int nt = 0; nt < 8; nt++) {
                const __half* bb = Ks + (nt * 8 + grp) * QP + kh + 2 * qid;
                mma_f16(s[nt], a0, a1, a2, a3,
                        *(const uint32_t*)(bb), *(const uint32_t*)(bb + 8));
            }
        }

        // ---- scale + causal mask (last two tiles only) + row max ----
        const int r_lo = q0 + wid * 16 + grp;
        const int r_hi = r_lo + 8;
        float lm0 = -1e30f, lm1 = -1e30f;
        const bool domask = (kt >= ntiles - 2);
        #pragma unroll
        for (int nt = 0; nt < 8; nt++) {
            const int cg = k0 + nt * 8 + 2 * qid;
            #pragma unroll
            for (int i = 0; i < 4; i++) s[nt][i] *= 0.125f;
            if (domask) {
                if (cg     > r_lo) s[nt][0] = -1e30f;
                if (cg + 1 > r_lo) s[nt][1] = -1e30f;
                if (cg     > r_hi) s[nt][2] = -1e30f;
                if (cg + 1 > r_hi) s[nt][3] = -1e30f;
            }
            lm0 = fmaxf(lm0, fmaxf(s[nt][0], s[nt][1]));
            lm1 = fmaxf(lm1, fmaxf(s[nt][2], s[nt][3]));
        }
        lm0 = fmaxf(lm0, __shfl_xor_sync(0xFFFFFFFFu, lm0, 1));
        lm0 = fmaxf(lm0, __shfl_xor_sync(0xFFFFFFFFu, lm0, 2));
        lm1 = fmaxf(lm1, __shfl_xor_sync(0xFFFFFFFFu, lm1, 1));
        lm1 = fmaxf(lm1, __shfl_xor_sync(0xFFFFFFFFu, lm1, 2));

        const float mn0 = fmaxf(m0, lm0), mn1 = fmaxf(m1, lm1);
        const float corr0 = __expf(m0 - mn0), corr1 = __expf(m1 - mn1);
        m0 = mn0; m1 = mn1;

        // ---- exp, row sums, stage P (fp16) ----
        float ls0 = 0.f, ls1 = 0.f;
        #pragma unroll
        for (int nt = 0; nt < 8; nt++) {
            float p0 = __expf(s[nt][0] - mn0);
            float p1 = __expf(s[nt][1] - mn0);
            float p2 = __expf(s[nt][2] - mn1);
            float p3 = __expf(s[nt][3] - mn1);
            ls0 += p0 + p1; ls1 += p2 + p3;
            *(__half2*)&Pw[grp * QP + nt * 8 + 2 * qid]       = __floats2half2_rn(p0, p1);
            *(__half2*)&Pw[(grp + 8) * QP + nt * 8 + 2 * qid] = __floats2half2_rn(p2, p3);
        }
        ls0 += __shfl_xor_sync(0xFFFFFFFFu, ls0, 1);
        ls0 += __shfl_xor_sync(0xFFFFFFFFu, ls0, 2);
        ls1 += __shfl_xor_sync(0xFFFFFFFFu, ls1, 1);
        ls1 += __shfl_xor_sync(0xFFFFFFFFu, ls1, 2);
        l0 = l0 * corr0 + ls0;
        l1 = l1 * corr1 + ls1;

        #pragma unroll
        for (int nt = 0; nt < 8; nt++) {
            o[nt][0] *= corr0; o[nt][1] *= corr0;
            o[nt][2] *= corr1; o[nt][3] *= corr1;
        }

        __syncwarp();

        // ---- O += P @ V ----
        #pragma unroll
        for (int ks = 0; ks < 4; ks++) {
            const int kh = ks * 16;
            const __half* ab = Pw + grp * QP + kh + 2 * qid;
            uint32_t a0 = *(const uint32_t*)(ab);
            uint32_t a1 = *(const uint32_t*)(ab + 8 * QP);
            uint32_t a2 = *(const uint32_t*)(ab + 8);
            uint32_t a3 = *(const uint32_t*)(ab + 8 * QP + 8);
            #pragma unroll
            for (int nt = 0; nt < 8; nt++) {
                const __half* bb = Vs + (nt * 8 + grp) * QP + kh + 2 * qid;
                mma_f16(o[nt], a0, a1, a2, a3,
                        *(const uint32_t*)(bb), *(const uint32_t*)(bb + 8));
            }
        }
        __syncthreads();   // KV stage free for reuse
    }

    // ---- epilogue: normalize, fp16-round, scatter to g_aoh [b*s, d] ----
    const int b = bh >> 4, h = bh & (NH - 1);
    const float inv0 = 1.f / l0, inv1 = 1.f / l1;
    const int s_lo = q0 + wid * 16 + grp;
    const int s_hi = s_lo + 8;
    #pragma unroll
    for (int nt = 0; nt < 8; nt++) {
        const int col = h * HD + nt * 8 + 2 * qid;
        *(__half2*)&g_aoh[((size_t)(b * SEQ + s_lo)) * DM + col] =
            __floats2half2_rn(o[nt][0] * inv0, o[nt][1] * inv0);
        *(__half2*)&g_aoh[((size_t)(b * SEQ + s_hi)) * DM + col] =
            __floats2half2_rn(o[nt][2] * inv1, o[nt][3] * inv1);
    }
}

// ---------------------------------------------------------------------------
extern "C" void kernel_launch(void* const* d_in, const int* in_sizes, int n_in,
                              void* d_out, int out_size)
{
    const float* x  = (const float*)d_in[0];
    const float* Wq = (const float*)d_in[1];
    const float* bq = (const float*)d_in[2];
    const float* Wk = (const float*)d_in[3];
    const float* bk = (const float*)d_in[4];
    const float* Wv = (const float*)d_in[5];
    const float* bv = (const float*)d_in[6];
    const float* Wo = (const float*)d_in[7];
    const float* bo = (const float*)d_in[8];

    cudaFuncSetAttribute(gemm_mma<0>,
                         cudaFuncAttributeMaxDynamicSharedMemorySize, GEMM_SMEM_BYTES);
    cudaFuncSetAttribute(gemm_mma<3>,
                         cudaFuncAttributeMaxDynamicSharedMemorySize, GEMM_SMEM_BYTES);
    cudaFuncSetAttribute(attn_mma,
                         cudaFuncAttributeMaxDynamicSharedMemorySize, ATTN_SMEM_BYTES);

    prep_x<<<MTOT * DM / 4 / 256, 256>>>(x);
    prep_wt<<<dim3(DM / 32, DM / 32, 4), 256>>>(Wq, Wk, Wv, Wo);

    gemm_mma<0><<<dim3(DM / 128, MTOT / 128, 3), 256, GEMM_SMEM_BYTES>>>(
        bq, bk, bv, nullptr);

    attn_mma<<<dim3(SEQ / 128, BATCH * NH), 256, ATTN_SMEM_BYTES>>>();

    gemm_mma<3><<<dim3(DM / 128, MTOT / 128, 1), 256, GEMM_SMEM_BYTES>>>(
        bo, nullptr, nullptr, (float*)d_out);
}

// round 14
// speedup vs baseline: 1.1031x; 1.1031x over previous
#include <cuda_runtime.h>
#include <cuda_fp16.h>
#include <cstdint>
#include <cstring>

#define DM    1024
#define NH    16
#define HD    64
#define BATCH 2
#define SEQ   2048
#define MTOT  (BATCH*SEQ)   // 4096

// Scratch (allocation-free rule: __device__ globals)
__device__ __half g_qh [(long long)BATCH*NH*SEQ*HD];  // [b,h,s,hd]
__device__ __half g_kh [(long long)BATCH*NH*SEQ*HD];  // [b,h,s,hd]
__device__ __half g_vt [(long long)BATCH*NH*HD*SEQ];  // [b,h,hd,s]  (transposed!)
__device__ __half g_aoh[(long long)MTOT*DM];          // [b*s, d]
__device__ __half g_xh [(long long)MTOT*DM];          // x as fp16
__device__ __half g_WhT[(long long)4*DM*DM];          // W^T: [w][n][k]

__device__ __forceinline__ uint32_t smem_u32(const void* p) {
    uint32_t a;
    asm("{ .reg .u64 t; cvta.to.shared.u64 t, %1; cvt.u32.u64 %0, t; }"
        : "=r"(a) : "l"(p));
    return a;
}

__device__ __forceinline__ void cp16(uint32_t dst, const void* src) {
    asm volatile("cp.async.cg.shared.global [%0], [%1], 16;"
                 :: "r"(dst), "l"(src) : "memory");
}
#define CP_COMMIT() asm volatile("cp.async.commit_group;" ::: "memory")
#define CP_WAIT(n)  asm volatile("cp.async.wait_group %0;" :: "n"(n) : "memory")

__device__ __forceinline__ void mma_f16(float c[4], uint32_t a0, uint32_t a1,
                                        uint32_t a2, uint32_t a3,
                                        uint32_t b0, uint32_t b1) {
    asm volatile(
        "mma.sync.aligned.m16n8k16.row.col.f32.f16.f16.f32 "
        "{%0,%1,%2,%3}, {%4,%5,%6,%7}, {%8,%9}, {%0,%1,%2,%3};"
        : "+f"(c[0]), "+f"(c[1]), "+f"(c[2]), "+f"(c[3])
        : "r"(a0), "r"(a1), "r"(a2), "r"(a3), "r"(b0), "r"(b1));
}

__device__ __forceinline__ float ex2f(float x) {
    float r;
    asm("ex2.approx.f32 %0, %1;" : "=f"(r) : "f"(x));
    return r;
}

__device__ __forceinline__ uint32_t pack_half2(float lo, float hi) {
    __half2 h = __floats2half2_rn(lo, hi);
    uint32_t u;
    memcpy(&u, &h, 4);
    return u;
}

// ===========================================================================
// Prep 1: x -> fp16.   Prep 2: W -> fp16 transposed [n][k].
// ===========================================================================
__global__ void __launch_bounds__(256)
prep_x(const float* __restrict__ x)
{
    const int i = blockIdx.x * blockDim.x + threadIdx.x;
    float4 v = ((const float4*)x)[i];
    ((__half2*)g_xh)[i * 2 + 0] = __floats2half2_rn(v.x, v.y);
    ((__half2*)g_xh)[i * 2 + 1] = __floats2half2_rn(v.z, v.w);
}

__global__ void __launch_bounds__(256)
prep_wt(const float* __restrict__ wq, const float* __restrict__ wk,
        const float* __restrict__ wv, const float* __restrict__ wo)
{
    __shared__ float s[32][33];
    const int w = blockIdx.z;
    const float* W = (w == 0) ? wq : (w == 1) ? wk : (w == 2) ? wv : wo;
    const int n0 = blockIdx.x * 32, k0 = blockIdx.y * 32;
    const int tx = threadIdx.x & 31, ty = threadIdx.x >> 5;   // 32 x 8
    #pragma unroll
    for (int r = 0; r < 4; r++)
        s[ty + r * 8][tx] = W[(size_t)(k0 + ty + r * 8) * DM + n0 + tx];
    __syncthreads();
    #pragma unroll
    for (int r = 0; r < 4; r++)
        g_WhT[(size_t)w * DM * DM + (size_t)(n0 + ty + r * 8) * DM + k0 + tx] =
            __float2half_rn(s[tx][ty + r * 8]);
}

// ===========================================================================
// FP16 mma.sync GEMM (unchanged from R11 — passing)
// ===========================================================================
#define APITCH 56
#define ATILEH (128*APITCH)
#define BUFH   (2*ATILEH)
#define NSTAGE 3
#define GEMM_SMEM_BYTES (NSTAGE*BUFH*2)   // 86016
#define NKT (DM/32)

template<int MODE>
__global__ void __launch_bounds__(256, 2)
gemm_mma(const float* __restrict__ b0,
         const float* __restrict__ b1,
         const float* __restrict__ b2,
         float* __restrict__ Cout)
{
    extern __shared__ __half smh[];
    const uint32_t sb = smem_u32(smh);

    const int t   = threadIdx.x;
    const int wid = t >> 5, lane = t & 31;
    const int grp = lane >> 2, qid = lane & 3;
    const int wr  = wid & 1, wc = wid >> 1;
    const int bn  = blockIdx.x * 128, bm = blockIdx.y * 128;
    const int z   = (MODE == 3) ? 3 : blockIdx.z;

    const __half* Ap = (MODE == 3) ? g_aoh : g_xh;
    const __half* Wt = g_WhT + (size_t)z * DM * DM;
    const float* bias = (MODE == 3) ? b0 : (z == 0) ? b0 : (z == 1) ? b1 : b2;

    float c[4][4][4];
    #pragma unroll
    for (int mt = 0; mt < 4; mt++)
        #pragma unroll
        for (int nt = 0; nt < 4; nt++)
            #pragma unroll
            for (int i = 0; i < 4; i++) c[mt][nt][i] = 0.f;

    auto loadA = [&](int p, int kt) {
        #pragma unroll
        for (int i = 0; i < 2; i++) {
            int idx = t + 256 * i;
            int row = idx >> 2, c4 = idx & 3;
            cp16(sb + (uint32_t)(p * BUFH + row * APITCH + c4 * 8) * 2,
                 &Ap[(size_t)(bm + row) * DM + kt * 32 + c4 * 8]);
        }
    };
    auto loadW = [&](int p, int kt) {
        #pragma unroll
        for (int i = 0; i < 2; i++) {
            int idx = t + 256 * i;
            int row = idx >> 2, c4 = idx & 3;
            cp16(sb + (uint32_t)(p * BUFH + ATILEH + row * APITCH + c4 * 8) * 2,
                 &Wt[(size_t)(bn + row) * DM + kt * 32 + c4 * 8]);
        }
    };

    loadA(0, 0); loadW(0, 0); CP_COMMIT();
    loadA(1, 1); loadW(1, 1); CP_COMMIT();

    int cs = 0, ls = 2;
    for (int kt = 0; kt < NKT; kt++) {
        if (kt + 1 < NKT) { CP_WAIT(1); } else { CP_WAIT(0); }
        __syncthreads();

        if (kt + 2 < NKT) {
            loadA(ls, kt + 2); loadW(ls, kt + 2); CP_COMMIT();
            ls = (ls + 1 == NSTAGE) ? 0 : ls + 1;
        }

        const __half* As = smh + cs * BUFH;
        const __half* Ws = smh + cs * BUFH + ATILEH;
        #pragma unroll
        for (int ks = 0; ks < 2; ks++) {
            const int kh = ks * 16;
            uint32_t af[4][4];
            #pragma unroll
            for (int mt = 0; mt < 4; mt++) {
                const __half* ab = As + (wr * 64 + mt * 16 + grp) * APITCH + kh + 2 * qid;
                af[mt][0] = *(const uint32_t*)(ab);
                af[mt][1] = *(const uint32_t*)(ab + 8 * APITCH);
                af[mt][2] = *(const uint32_t*)(ab + 8);
                af[mt][3] = *(const uint32_t*)(ab + 8 * APITCH + 8);
            }
            uint32_t bf[4][2];
            #pragma unroll
            for (int nt = 0; nt < 4; nt++) {
                const __half* bb = Ws + (wc * 32 + nt * 8 + grp) * APITCH + kh + 2 * qid;
                bf[nt][0] = *(const uint32_t*)(bb);
                bf[nt][1] = *(const uint32_t*)(bb + 8);
            }
            #pragma unroll
            for (int mt = 0; mt < 4; mt++)
                #pragma unroll
                for (int nt = 0; nt < 4; nt++)
                    mma_f16(c[mt][nt], af[mt][0], af[mt][1], af[mt][2], af[mt][3],
                            bf[nt][0], bf[nt][1]);
        }
        cs = (cs + 1 == NSTAGE) ? 0 : cs + 1;
    }

    #pragma unroll
    for (int mt = 0; mt < 4; mt++) {
        #pragma unroll
        for (int nt = 0; nt < 4; nt++) {
            const int gc = bn + wc * 32 + nt * 8 + 2 * qid;
            const float bx = bias[gc], by = bias[gc + 1];
            #pragma unroll
            for (int half = 0; half < 2; half++) {
                const int gr = bm + wr * 64 + mt * 16 + grp + half * 8;
                const float vx = c[mt][nt][half * 2 + 0] + bx;
                const float vy = c[mt][nt][half * 2 + 1] + by;
                if (MODE == 3) {
                    float2 v; v.x = vx; v.y = vy;
                    *(float2*)&Cout[(size_t)gr * DM + gc] = v;
                } else {
                    const int b = gr >> 11, s = gr & (SEQ - 1);
                    const int h = gc >> 6,  hd = gc & (HD - 1);
                    if (z == 0) {
                        *(__half2*)&g_qh[((size_t)((b * NH + h) * SEQ + s)) * HD + hd] =
                            __floats2half2_rn(vx, vy);
                    } else if (z == 1) {
                        *(__half2*)&g_kh[((size_t)((b * NH + h) * SEQ + s)) * HD + hd] =
                            __floats2half2_rn(vx, vy);
                    } else {
                        __half* vtp = g_vt + ((size_t)(b * NH + h) * HD) * SEQ;
                        vtp[(size_t)(hd + 0) * SEQ + s] = __float2half_rn(vx);
                        vtp[(size_t)(hd + 1) * SEQ + s] = __float2half_rn(vy);
                    }
                }
            }
        }
    }
}

// ===========================================================================
// FP16 mma.sync flash attention.  BQ=BK=64, 128 threads = 4 warps.
// P kept entirely in registers (S-accum layout == PV A-fragment layout).
// One barrier per k-tile; 2-stage cp.async K/V(transposed).
// grid: (SEQ/64, BATCH*NH), reversed qt.
// ===========================================================================
#define QP 72                         // half pitch: 144 B
#define SMQ   0                       // 64*72 = 4608 halves
#define SMKV  (64*QP)                 // 4608
#define KVH   (2*64*QP)               // 9216 halves per stage (K + Vt)
#define ATTN_H (SMKV + 2*KVH)         // 23040 halves
#define ATTN_SMEM_BYTES (ATTN_H*2)    // 46080

__global__ void __launch_bounds__(128)
attn_mma()
{
    extern __shared__ __half smh[];
    const uint32_t sb = smem_u32(smh);

    const int t    = threadIdx.x;
    const int wid  = t >> 5, lane = t & 31;
    const int grp  = lane >> 2, qid = lane & 3;
    const int qt   = gridDim.x - 1 - blockIdx.x;
    const int bh   = blockIdx.y;
    const int q0   = qt * 64;

    const __half* Qg  = g_qh + ((size_t)bh * SEQ + q0) * HD;
    const __half* Kg  = g_kh + (size_t)bh * SEQ * HD;
    const __half* Vtg = g_vt + (size_t)bh * HD * SEQ;

    auto loadKV = [&](int p, int kt) {
        const int k0 = kt * 64;
        const uint32_t kb = sb + (uint32_t)(SMKV + p * KVH) * 2;
        #pragma unroll
        for (int i = 0; i < 4; i++) {
            int idx = t + 128 * i;
            int row = idx >> 3, c8 = idx & 7;       // K: 64 rows x 8 chunks
            cp16(kb + (uint32_t)(row * QP + c8 * 8) * 2,
                 &Kg[(size_t)(k0 + row) * HD + c8 * 8]);
        }
        #pragma unroll
        for (int i = 0; i < 4; i++) {
            int idx = t + 128 * i;
            int d = idx >> 3, c8 = idx & 7;         // Vt: 64 d-rows x 8 s-chunks
            cp16(kb + (uint32_t)(64 * QP + d * QP + c8 * 8) * 2,
                 &Vtg[(size_t)d * SEQ + k0 + c8 * 8]);
        }
    };

    // Q tile + first K/V stage in one group
    #pragma unroll
    for (int i = 0; i < 4; i++) {
        int idx = t + 128 * i;
        int row = idx >> 3, c8 = idx & 7;
        cp16(sb + (uint32_t)(SMQ + row * QP + c8 * 8) * 2,
             &Qg[(size_t)row * HD + c8 * 8]);
    }
    loadKV(0, 0);
    CP_COMMIT();

    float o[8][4];
    #pragma unroll
    for (int nt = 0; nt < 8; nt++)
        #pragma unroll
        for (int i = 0; i < 4; i++) o[nt][i] = 0.f;
    float m0 = -1e30f, m1 = -1e30f, l0 = 0.f, l1 = 0.f;

    const float CE = 0.125f * 1.44269504f;   // scale * log2(e)

    const int ntiles = qt + 1;
    for (int kt = 0; kt < ntiles; kt++) {
        const int p = kt & 1;
        CP_WAIT(0);
        __syncthreads();   // stage p visible; all warps done reading stage p^1
        if (kt + 1 < ntiles) { loadKV(p ^ 1, kt + 1); CP_COMMIT(); }

        const int k0 = kt * 64;
        const __half* Ks = smh + SMKV + p * KVH;
        const __half* Vs = Ks + 64 * QP;

        // ---- S = Q @ K^T (raw, unscaled) ----
        float s[8][4];
        #pragma unroll
        for (int nt = 0; nt < 8; nt++)
            #pragma unroll
            for (int i = 0; i < 4; i++) s[nt][i] = 0.f;

        const __half* Qs = smh + SMQ + (wid * 16) * QP;
        #pragma unroll
        for (int ks = 0; ks < 4; ks++) {
            const int kh = ks * 16;
            const __half* ab = Qs + grp * QP + kh + 2 * qid;
            uint32_t a0 = *(const uint32_t*)(ab);
            uint32_t a1 = *(const uint32_t*)(ab + 8 * QP);
            uint32_t a2 = *(const uint32_t*)(ab + 8);
            uint32_t a3 = *(const uint32_t*)(ab + 8 * QP + 8);
            #pragma unroll
            for (int nt = 0; nt < 8; nt++) {
                const __half* bb = Ks + (nt * 8 + grp) * QP + kh + 2 * qid;
                mma_f16(s[nt], a0, a1, a2, a3,
                        *(const uint32_t*)(bb), *(const uint32_t*)(bb + 8));
            }
        }

        // ---- causal mask (diagonal tile only) + row max on raw S ----
        const int r_lo = q0 + wid * 16 + grp;
        const int r_hi = r_lo + 8;
        float lm0 = -1e30f, lm1 = -1e30f;
        const bool domask = (kt == ntiles - 1);
        #pragma unroll
        for (int nt = 0; nt < 8; nt++) {
            const int cg = k0 + nt * 8 + 2 * qid;
            if (domask) {
                if (cg     > r_lo) s[nt][0] = -1e30f;
                if (cg + 1 > r_lo) s[nt][1] = -1e30f;
                if (cg     > r_hi) s[nt][2] = -1e30f;
                if (cg + 1 > r_hi) s[nt][3] = -1e30f;
            }
            lm0 = fmaxf(lm0, fmaxf(s[nt][0], s[nt][1]));
            lm1 = fmaxf(lm1, fmaxf(s[nt][2], s[nt][3]));
        }
        lm0 = fmaxf(lm0, __shfl_xor_sync(0xFFFFFFFFu, lm0, 1));
        lm0 = fmaxf(lm0, __shfl_xor_sync(0xFFFFFFFFu, lm0, 2));
        lm1 = fmaxf(lm1, __shfl_xor_sync(0xFFFFFFFFu, lm1, 1));
        lm1 = fmaxf(lm1, __shfl_xor_sync(0xFFFFFFFFu, lm1, 2));

        const float mn0 = fmaxf(m0, lm0), mn1 = fmaxf(m1, lm1);
        const float mc0 = mn0 * CE, mc1 = mn1 * CE;
        const float corr0 = ex2f(fmaf(m0, CE, -mc0));
        const float corr1 = ex2f(fmaf(m1, CE, -mc1));
        m0 = mn0; m1 = mn1;

        // ---- exp + row sums + P fragments IN REGISTERS ----
        float ls0 = 0.f, ls1 = 0.f;
        uint32_t pp[8][2];
        #pragma unroll
        for (int nt = 0; nt < 8; nt++) {
            float p0 = ex2f(fmaf(s[nt][0], CE, -mc0));
            float p1 = ex2f(fmaf(s[nt][1], CE, -mc0));
            float p2 = ex2f(fmaf(s[nt][2], CE, -mc1));
            float p3 = ex2f(fmaf(s[nt][3], CE, -mc1));
            ls0 += p0 + p1; ls1 += p2 + p3;
            pp[nt][0] = pack_half2(p0, p1);
            pp[nt][1] = pack_half2(p2, p3);
        }
        ls0 += __shfl_xor_sync(0xFFFFFFFFu, ls0, 1);
        ls0 += __shfl_xor_sync(0xFFFFFFFFu, ls0, 2);
        ls1 += __shfl_xor_sync(0xFFFFFFFFu, ls1, 1);
        ls1 += __shfl_xor_sync(0xFFFFFFFFu, ls1, 2);
        l0 = l0 * corr0 + ls0;
        l1 = l1 * corr1 + ls1;

        #pragma unroll
        for (int nt = 0; nt < 8; nt++) {
            o[nt][0] *= corr0; o[nt][1] *= corr0;
            o[nt][2] *= corr1; o[nt][3] *= corr1;
        }

        // ---- O += P @ V : A-fragments straight from pp ----
        #pragma unroll
        for (int ks = 0; ks < 4; ks++) {
            const int kh = ks * 16;
            uint32_t a0 = pp[2 * ks][0];
            uint32_t a1 = pp[2 * ks][1];
            uint32_t a2 = pp[2 * ks + 1][0];
            uint32_t a3 = pp[2 * ks + 1][1];
            #pragma unroll
            for (int nt = 0; nt < 8; nt++) {
                const __half* bb = Vs + (nt * 8 + grp) * QP + kh + 2 * qid;
                mma_f16(o[nt], a0, a1, a2, a3,
                        *(const uint32_t*)(bb), *(const uint32_t*)(bb + 8));
            }
        }
        // no end-of-loop barrier: next iteration's top barrier protects reuse
    }

    // ---- epilogue: normalize, fp16-round, scatter to g_aoh [b*s, d] ----
    const int b = bh >> 4, h = bh & (NH - 1);
    const float inv0 = 1.f / l0, inv1 = 1.f / l1;
    const int s_lo = q0 + wid * 16 + grp;
    const int s_hi = s_lo + 8;
    #pragma unroll
    for (int nt = 0; nt < 8; nt++) {
        const int col = h * HD + nt * 8 + 2 * qid;
        *(__half2*)&g_aoh[((size_t)(b * SEQ + s_lo)) * DM + col] =
            __floats2half2_rn(o[nt][0] * inv0, o[nt][1] * inv0);
        *(__half2*)&g_aoh[((size_t)(b * SEQ + s_hi)) * DM + col] =
            __floats2half2_rn(o[nt][2] * inv1, o[nt][3] * inv1);
    }
}

// ---------------------------------------------------------------------------
extern "C" void kernel_launch(void* const* d_in, const int* in_sizes, int n_in,
                              void* d_out, int out_size)
{
    const float* x  = (const float*)d_in[0];
    const float* Wq = (const float*)d_in[1];
    const float* bq = (const float*)d_in[2];
    const float* Wk = (const float*)d_in[3];
    const float* bk = (const float*)d_in[4];
    const float* Wv = (const float*)d_in[5];
    const float* bv = (const float*)d_in[6];
    const float* Wo = (const float*)d_in[7];
    const float* bo = (const float*)d_in[8];

    cudaFuncSetAttribute(gemm_mma<0>,
                         cudaFuncAttributeMaxDynamicSharedMemorySize, GEMM_SMEM_BYTES);
    cudaFuncSetAttribute(gemm_mma<3>,
                         cudaFuncAttributeMaxDynamicSharedMemorySize, GEMM_SMEM_BYTES);
    cudaFuncSetAttribute(attn_mma,
                         cudaFuncAttributeMaxDynamicSharedMemorySize, ATTN_SMEM_BYTES);

    prep_x<<<MTOT * DM / 4 / 256, 256>>>(x);
    prep_wt<<<dim3(DM / 32, DM / 32, 4), 256>>>(Wq, Wk, Wv, Wo);

    gemm_mma<0><<<dim3(DM / 128, MTOT / 128, 3), 256, GEMM_SMEM_BYTES>>>(
        bq, bk, bv, nullptr);

    attn_mma<<<dim3(SEQ / 64, BATCH * NH), 128, ATTN_SMEM_BYTES>>>();

    gemm_mma<3><<<dim3(DM / 128, MTOT / 128, 1), 256, GEMM_SMEM_BYTES>>>(
        bo, nullptr, nullptr, (float*)d_out);
}

// round 15
// speedup vs baseline: 1.2168x; 1.1031x over previous
#include <cuda_runtime.h>
#include <cuda_fp16.h>
#include <cstdint>
#include <cstring>

#define DM    1024
#define NH    16
#define HD    64
#define BATCH 2
#define SEQ   2048
#define MTOT  (BATCH*SEQ)   // 4096

// Scratch (allocation-free rule: __device__ globals)
__device__ __half g_qh [(long long)BATCH*NH*SEQ*HD];  // [b,h,s,hd]
__device__ __half g_kh [(long long)BATCH*NH*SEQ*HD];  // [b,h,s,hd]
__device__ __half g_vt [(long long)BATCH*NH*HD*SEQ];  // [b,h,hd,s]  (transposed!)
__device__ __half g_aoh[(long long)MTOT*DM];          // [b*s, d]
__device__ __half g_xh [(long long)MTOT*DM];          // x as fp16
__device__ __half g_WhT[(long long)4*DM*DM];          // W^T: [w][n][k]

__device__ __forceinline__ uint32_t smem_u32(const void* p) {
    uint32_t a;
    asm("{ .reg .u64 t; cvta.to.shared.u64 t, %1; cvt.u32.u64 %0, t; }"
        : "=r"(a) : "l"(p));
    return a;
}

__device__ __forceinline__ void cp16(uint32_t dst, const void* src) {
    asm volatile("cp.async.cg.shared.global [%0], [%1], 16;"
                 :: "r"(dst), "l"(src) : "memory");
}
#define CP_COMMIT() asm volatile("cp.async.commit_group;" ::: "memory")
#define CP_WAIT(n)  asm volatile("cp.async.wait_group %0;" :: "n"(n) : "memory")

__device__ __forceinline__ void mma_f16(float c[4], uint32_t a0, uint32_t a1,
                                        uint32_t a2, uint32_t a3,
                                        uint32_t b0, uint32_t b1) {
    asm volatile(
        "mma.sync.aligned.m16n8k16.row.col.f32.f16.f16.f32 "
        "{%0,%1,%2,%3}, {%4,%5,%6,%7}, {%8,%9}, {%0,%1,%2,%3};"
        : "+f"(c[0]), "+f"(c[1]), "+f"(c[2]), "+f"(c[3])
        : "r"(a0), "r"(a1), "r"(a2), "r"(a3), "r"(b0), "r"(b1));
}

__device__ __forceinline__ void ldsm_x4(uint32_t& r0, uint32_t& r1,
                                        uint32_t& r2, uint32_t& r3, uint32_t addr) {
    asm volatile("ldmatrix.sync.aligned.m8n8.x4.shared.b16 {%0,%1,%2,%3}, [%4];"
                 : "=r"(r0), "=r"(r1), "=r"(r2), "=r"(r3) : "r"(addr));
}

__device__ __forceinline__ float ex2f(float x) {
    float r;
    asm("ex2.approx.f32 %0, %1;" : "=f"(r) : "f"(x));
    return r;
}

__device__ __forceinline__ uint32_t pack_half2(float lo, float hi) {
    __half2 h = __floats2half2_rn(lo, hi);
    uint32_t u;
    memcpy(&u, &h, 4);
    return u;
}

// ===========================================================================
// Prep 1: x -> fp16.   Prep 2: W -> fp16 transposed [n][k].
// ===========================================================================
__global__ void __launch_bounds__(256)
prep_x(const float* __restrict__ x)
{
    const int i = blockIdx.x * blockDim.x + threadIdx.x;
    float4 v = ((const float4*)x)[i];
    ((__half2*)g_xh)[i * 2 + 0] = __floats2half2_rn(v.x, v.y);
    ((__half2*)g_xh)[i * 2 + 1] = __floats2half2_rn(v.z, v.w);
}

__global__ void __launch_bounds__(256)
prep_wt(const float* __restrict__ wq, const float* __restrict__ wk,
        const float* __restrict__ wv, const float* __restrict__ wo)
{
    __shared__ float s[32][33];
    const int w = blockIdx.z;
    const float* W = (w == 0) ? wq : (w == 1) ? wk : (w == 2) ? wv : wo;
    const int n0 = blockIdx.x * 32, k0 = blockIdx.y * 32;
    const int tx = threadIdx.x & 31, ty = threadIdx.x >> 5;   // 32 x 8
    #pragma unroll
    for (int r = 0; r < 4; r++)
        s[ty + r * 8][tx] = W[(size_t)(k0 + ty + r * 8) * DM + n0 + tx];
    __syncthreads();
    #pragma unroll
    for (int r = 0; r < 4; r++)
        g_WhT[(size_t)w * DM * DM + (size_t)(n0 + ty + r * 8) * DM + k0 + tx] =
            __float2half_rn(s[tx][ty + r * 8]);
}

// ===========================================================================
// FP16 mma.sync GEMM, 3-stage cp.async, ldmatrix fragment loads.
// ===========================================================================
#define APITCH 56
#define ATILEH (128*APITCH)
#define BUFH   (2*ATILEH)
#define NSTAGE 3
#define GEMM_SMEM_BYTES (NSTAGE*BUFH*2)   // 86016
#define NKT (DM/32)

template<int MODE>
__global__ void __launch_bounds__(256, 2)
gemm_mma(const float* __restrict__ b0,
         const float* __restrict__ b1,
         const float* __restrict__ b2,
         float* __restrict__ Cout)
{
    extern __shared__ __half smh[];
    const uint32_t sb = smem_u32(smh);

    const int t   = threadIdx.x;
    const int wid = t >> 5, lane = t & 31;
    const int grp = lane >> 2, qid = lane & 3;
    const int wr  = wid & 1, wc = wid >> 1;
    const int bn  = blockIdx.x * 128, bm = blockIdx.y * 128;
    const int z   = (MODE == 3) ? 3 : blockIdx.z;

    const __half* Ap = (MODE == 3) ? g_aoh : g_xh;
    const __half* Wt = g_WhT + (size_t)z * DM * DM;
    const float* bias = (MODE == 3) ? b0 : (z == 0) ? b0 : (z == 1) ? b1 : b2;

    // lane-invariant ldmatrix offsets (bytes)
    const int lm = lane >> 3, lr = lane & 7;
    const uint32_t aoff2 = (uint32_t)((((lm & 1) * 8 + lr) * APITCH + (lm >> 1) * 8) * 2);
    const uint32_t boff2 = (uint32_t)((((lm >> 1) * 8 + lr) * APITCH + (lm & 1) * 8) * 2);

    float c[4][4][4];
    #pragma unroll
    for (int mt = 0; mt < 4; mt++)
        #pragma unroll
        for (int nt = 0; nt < 4; nt++)
            #pragma unroll
            for (int i = 0; i < 4; i++) c[mt][nt][i] = 0.f;

    auto loadA = [&](int p, int kt) {
        #pragma unroll
        for (int i = 0; i < 2; i++) {
            int idx = t + 256 * i;
            int row = idx >> 2, c4 = idx & 3;
            cp16(sb + (uint32_t)(p * BUFH + row * APITCH + c4 * 8) * 2,
                 &Ap[(size_t)(bm + row) * DM + kt * 32 + c4 * 8]);
        }
    };
    auto loadW = [&](int p, int kt) {
        #pragma unroll
        for (int i = 0; i < 2; i++) {
            int idx = t + 256 * i;
            int row = idx >> 2, c4 = idx & 3;
            cp16(sb + (uint32_t)(p * BUFH + ATILEH + row * APITCH + c4 * 8) * 2,
                 &Wt[(size_t)(bn + row) * DM + kt * 32 + c4 * 8]);
        }
    };

    loadA(0, 0); loadW(0, 0); CP_COMMIT();
    loadA(1, 1); loadW(1, 1); CP_COMMIT();

    int cs = 0, ls = 2;
    for (int kt = 0; kt < NKT; kt++) {
        if (kt + 1 < NKT) { CP_WAIT(1); } else { CP_WAIT(0); }
        __syncthreads();

        if (kt + 2 < NKT) {
            loadA(ls, kt + 2); loadW(ls, kt + 2); CP_COMMIT();
            ls = (ls + 1 == NSTAGE) ? 0 : ls + 1;
        }

        const uint32_t As_b = sb + (uint32_t)(cs * BUFH) * 2;
        const uint32_t Ws_b = As_b + (uint32_t)ATILEH * 2;
        #pragma unroll
        for (int ks = 0; ks < 2; ks++) {
            const int kh = ks * 16;
            uint32_t af[4][4];
            #pragma unroll
            for (int mt = 0; mt < 4; mt++)
                ldsm_x4(af[mt][0], af[mt][1], af[mt][2], af[mt][3],
                        As_b + (uint32_t)(((wr * 64 + mt * 16) * APITCH + kh) * 2) + aoff2);
            uint32_t bf[4][2];
            #pragma unroll
            for (int ntb = 0; ntb < 4; ntb += 2)
                ldsm_x4(bf[ntb][0], bf[ntb][1], bf[ntb + 1][0], bf[ntb + 1][1],
                        Ws_b + (uint32_t)(((wc * 32 + ntb * 8) * APITCH + kh) * 2) + boff2);
            #pragma unroll
            for (int mt = 0; mt < 4; mt++)
                #pragma unroll
                for (int nt = 0; nt < 4; nt++)
                    mma_f16(c[mt][nt], af[mt][0], af[mt][1], af[mt][2], af[mt][3],
                            bf[nt][0], bf[nt][1]);
        }
        cs = (cs + 1 == NSTAGE) ? 0 : cs + 1;
    }

    #pragma unroll
    for (int mt = 0; mt < 4; mt++) {
        #pragma unroll
        for (int nt = 0; nt < 4; nt++) {
            const int gc = bn + wc * 32 + nt * 8 + 2 * qid;
            const float bx = bias[gc], by = bias[gc + 1];
            #pragma unroll
            for (int half = 0; half < 2; half++) {
                const int gr = bm + wr * 64 + mt * 16 + grp + half * 8;
                const float vx = c[mt][nt][half * 2 + 0] + bx;
                const float vy = c[mt][nt][half * 2 + 1] + by;
                if (MODE == 3) {
                    float2 v; v.x = vx; v.y = vy;
                    *(float2*)&Cout[(size_t)gr * DM + gc] = v;
                } else {
                    const int b = gr >> 11, s = gr & (SEQ - 1);
                    const int h = gc >> 6,  hd = gc & (HD - 1);
                    if (z == 0) {
                        *(__half2*)&g_qh[((size_t)((b * NH + h) * SEQ + s)) * HD + hd] =
                            __floats2half2_rn(vx, vy);
                    } else if (z == 1) {
                        *(__half2*)&g_kh[((size_t)((b * NH + h) * SEQ + s)) * HD + hd] =
                            __floats2half2_rn(vx, vy);
                    } else {
                        __half* vtp = g_vt + ((size_t)(b * NH + h) * HD) * SEQ;
                        vtp[(size_t)(hd + 0) * SEQ + s] = __float2half_rn(vx);
                        vtp[(size_t)(hd + 1) * SEQ + s] = __float2half_rn(vy);
                    }
                }
            }
        }
    }
}

// ===========================================================================
// FP16 mma.sync flash attention.  BQ=BK=64, 128 threads = 4 warps.
// P in registers; ldmatrix fragment loads; one barrier per k-tile;
// 2-stage cp.async K/V(transposed).  grid: (SEQ/64, BATCH*NH), reversed qt.
// ===========================================================================
#define QP 72                         // half pitch: 144 B
#define SMQ   0                       // 64*72 = 4608 halves
#define SMKV  (64*QP)                 // 4608
#define KVH   (2*64*QP)               // 9216 halves per stage (K + Vt)
#define ATTN_H (SMKV + 2*KVH)         // 23040 halves
#define ATTN_SMEM_BYTES (ATTN_H*2)    // 46080

__global__ void __launch_bounds__(128)
attn_mma()
{
    extern __shared__ __half smh[];
    const uint32_t sb = smem_u32(smh);

    const int t    = threadIdx.x;
    const int wid  = t >> 5, lane = t & 31;
    const int grp  = lane >> 2, qid = lane & 3;
    const int qt   = gridDim.x - 1 - blockIdx.x;
    const int bh   = blockIdx.y;
    const int q0   = qt * 64;

    const __half* Qg  = g_qh + ((size_t)bh * SEQ + q0) * HD;
    const __half* Kg  = g_kh + (size_t)bh * SEQ * HD;
    const __half* Vtg = g_vt + (size_t)bh * HD * SEQ;

    // lane-invariant ldmatrix offsets (bytes), pitch QP
    const int lm = lane >> 3, lr = lane & 7;
    const uint32_t qoff2 = (uint32_t)((((lm & 1) * 8 + lr) * QP + (lm >> 1) * 8) * 2);
    const uint32_t boff2 = (uint32_t)((((lm >> 1) * 8 + lr) * QP + (lm & 1) * 8) * 2);

    auto loadKV = [&](int p, int kt) {
        const int k0 = kt * 64;
        const uint32_t kb = sb + (uint32_t)(SMKV + p * KVH) * 2;
        #pragma unroll
        for (int i = 0; i < 4; i++) {
            int idx = t + 128 * i;
            int row = idx >> 3, c8 = idx & 7;       // K: 64 rows x 8 chunks
            cp16(kb + (uint32_t)(row * QP + c8 * 8) * 2,
                 &Kg[(size_t)(k0 + row) * HD + c8 * 8]);
        }
        #pragma unroll
        for (int i = 0; i < 4; i++) {
            int idx = t + 128 * i;
            int d = idx >> 3, c8 = idx & 7;         // Vt: 64 d-rows x 8 s-chunks
            cp16(kb + (uint32_t)(64 * QP + d * QP + c8 * 8) * 2,
                 &Vtg[(size_t)d * SEQ + k0 + c8 * 8]);
        }
    };

    // Q tile + first K/V stage in one group
    #pragma unroll
    for (int i = 0; i < 4; i++) {
        int idx = t + 128 * i;
        int row = idx >> 3, c8 = idx & 7;
        cp16(sb + (uint32_t)(SMQ + row * QP + c8 * 8) * 2,
             &Qg[(size_t)row * HD + c8 * 8]);
    }
    loadKV(0, 0);
    CP_COMMIT();

    float o[8][4];
    #pragma unroll
    for (int nt = 0; nt < 8; nt++)
        #pragma unroll
        for (int i = 0; i < 4; i++) o[nt][i] = 0.f;
    float m0 = -1e30f, m1 = -1e30f, l0 = 0.f, l1 = 0.f;

    const float CE = 0.125f * 1.44269504f;   // scale * log2(e)

    const int ntiles = qt + 1;
    for (int kt = 0; kt < ntiles; kt++) {
        const int p = kt & 1;
        CP_WAIT(0);
        __syncthreads();   // stage p visible; all warps done reading stage p^1
        if (kt + 1 < ntiles) { loadKV(p ^ 1, kt + 1); CP_COMMIT(); }

        const int k0 = kt * 64;
        const uint32_t Ks_b = sb + (uint32_t)(SMKV + p * KVH) * 2;
        const uint32_t Vs_b = Ks_b + (uint32_t)(64 * QP) * 2;
        const uint32_t Qs_b = sb + (uint32_t)(SMQ + wid * 16 * QP) * 2;

        // ---- S = Q @ K^T (raw, unscaled) ----
        float s[8][4];
        #pragma unroll
        for (int nt = 0; nt < 8; nt++)
            #pragma unroll
            for (int i = 0; i < 4; i++) s[nt][i] = 0.f;

        #pragma unroll
        for (int ks = 0; ks < 4; ks++) {
            const int kh = ks * 16;
            uint32_t a0, a1, a2, a3;
            ldsm_x4(a0, a1, a2, a3, Qs_b + (uint32_t)(kh * 2) + qoff2);
            #pragma unroll
            for (int ntb = 0; ntb < 8; ntb += 2) {
                uint32_t b0, b1, b2, b3;
                ldsm_x4(b0, b1, b2, b3,
                        Ks_b + (uint32_t)((ntb * 8 * QP + kh) * 2) + boff2);
                mma_f16(s[ntb],     a0, a1, a2, a3, b0, b1);
                mma_f16(s[ntb + 1], a0, a1, a2, a3, b2, b3);
            }
        }

        // ---- causal mask (diagonal tile only) + row max on raw S ----
        const int r_lo = q0 + wid * 16 + grp;
        const int r_hi = r_lo + 8;
        float lm0 = -1e30f, lm1 = -1e30f;
        const bool domask = (kt == ntiles - 1);
        #pragma unroll
        for (int nt = 0; nt < 8; nt++) {
            const int cg = k0 + nt * 8 + 2 * qid;
            if (domask) {
                if (cg     > r_lo) s[nt][0] = -1e30f;
                if (cg + 1 > r_lo) s[nt][1] = -1e30f;
                if (cg     > r_hi) s[nt][2] = -1e30f;
                if (cg + 1 > r_hi) s[nt][3] = -1e30f;
            }
            lm0 = fmaxf(lm0, fmaxf(s[nt][0], s[nt][1]));
            lm1 = fmaxf(lm1, fmaxf(s[nt][2], s[nt][3]));
        }
        lm0 = fmaxf(lm0, __shfl_xor_sync(0xFFFFFFFFu, lm0, 1));
        lm0 = fmaxf(lm0, __shfl_xor_sync(0xFFFFFFFFu, lm0, 2));
        lm1 = fmaxf(lm1, __shfl_xor_sync(0xFFFFFFFFu, lm1, 1));
        lm1 = fmaxf(lm1, __shfl_xor_sync(0xFFFFFFFFu, lm1, 2));

        const float mn0 = fmaxf(m0, lm0), mn1 = fmaxf(m1, lm1);
        const float mc0 = mn0 * CE, mc1 = mn1 * CE;
        const float corr0 = ex2f(fmaf(m0, CE, -mc0));
        const float corr1 = ex2f(fmaf(m1, CE, -mc1));
        m0 = mn0; m1 = mn1;

        // ---- exp + row sums + P fragments IN REGISTERS ----
        float ls0 = 0.f, ls1 = 0.f;
        uint32_t pp[8][2];
        #pragma unroll
        for (int nt = 0; nt < 8; nt++) {
            float p0 = ex2f(fmaf(s[nt][0], CE, -mc0));
            float p1 = ex2f(fmaf(s[nt][1], CE, -mc0));
            float p2 = ex2f(fmaf(s[nt][2], CE, -mc1));
            float p3 = ex2f(fmaf(s[nt][3], CE, -mc1));
            ls0 += p0 + p1; ls1 += p2 + p3;
            pp[nt][0] = pack_half2(p0, p1);
            pp[nt][1] = pack_half2(p2, p3);
        }
        ls0 += __shfl_xor_sync(0xFFFFFFFFu, ls0, 1);
        ls0 += __shfl_xor_sync(0xFFFFFFFFu, ls0, 2);
        ls1 += __shfl_xor_sync(0xFFFFFFFFu, ls1, 1);
        ls1 += __shfl_xor_sync(0xFFFFFFFFu, ls1, 2);
        l0 = l0 * corr0 + ls0;
        l1 = l1 * corr1 + ls1;

        #pragma unroll
        for (int nt = 0; nt < 8; nt++) {
            o[nt][0] *= corr0; o[nt][1] *= corr0;
            o[nt][2] *= corr1; o[nt][3] *= corr1;
        }

        // ---- O += P @ V : A-fragments from pp, B via ldmatrix ----
        #pragma unroll
        for (int ks = 0; ks < 4; ks++) {
            const int kh = ks * 16;
            uint32_t a0 = pp[2 * ks][0];
            uint32_t a1 = pp[2 * ks][1];
            uint32_t a2 = pp[2 * ks + 1][0];
            uint32_t a3 = pp[2 * ks + 1][1];
            #pragma unroll
            for (int ntb = 0; ntb < 8; ntb += 2) {
                uint32_t b0, b1, b2, b3;
                ldsm_x4(b0, b1, b2, b3,
                        Vs_b + (uint32_t)((ntb * 8 * QP + kh) * 2) + boff2);
                mma_f16(o[ntb],     a0, a1, a2, a3, b0, b1);
                mma_f16(o[ntb + 1], a0, a1, a2, a3, b2, b3);
            }
        }
        // no end-of-loop barrier: next iteration's top barrier protects reuse
    }

    // ---- epilogue: normalize, fp16-round, scatter to g_aoh [b*s, d] ----
    const int b = bh >> 4, h = bh & (NH - 1);
    const float inv0 = 1.f / l0, inv1 = 1.f / l1;
    const int s_lo = q0 + wid * 16 + grp;
    const int s_hi = s_lo + 8;
    #pragma unroll
    for (int nt = 0; nt < 8; nt++) {
        const int col = h * HD + nt * 8 + 2 * qid;
        *(__half2*)&g_aoh[((size_t)(b * SEQ + s_lo)) * DM + col] =
            __floats2half2_rn(o[nt][0] * inv0, o[nt][1] * inv0);
        *(__half2*)&g_aoh[((size_t)(b * SEQ + s_hi)) * DM + col] =
            __floats2half2_rn(o[nt][2] * inv1, o[nt][3] * inv1);
    }
}

// ---------------------------------------------------------------------------
extern "C" void kernel_launch(void* const* d_in, const int* in_sizes, int n_in,
                              void* d_out, int out_size)
{
    const float* x  = (const float*)d_in[0];
    const float* Wq = (const float*)d_in[1];
    const float* bq = (const float*)d_in[2];
    const float* Wk = (const float*)d_in[3];
    const float* bk = (const float*)d_in[4];
    const float* Wv = (const float*)d_in[5];
    const float* bv = (const float*)d_in[6];
    const float* Wo = (const float*)d_in[7];
    const float* bo = (const float*)d_in[8];

    cudaFuncSetAttribute(gemm_mma<0>,
                         cudaFuncAttributeMaxDynamicSharedMemorySize, GEMM_SMEM_BYTES);
    cudaFuncSetAttribute(gemm_mma<3>,
                         cudaFuncAttributeMaxDynamicSharedMemorySize, GEMM_SMEM_BYTES);
    cudaFuncSetAttribute(attn_mma,
                         cudaFuncAttributeMaxDynamicSharedMemorySize, ATTN_SMEM_BYTES);

    prep_x<<<MTOT * DM / 4 / 256, 256>>>(x);
    prep_wt<<<dim3(DM / 32, DM / 32, 4), 256>>>(Wq, Wk, Wv, Wo);

    gemm_mma<0><<<dim3(DM / 128, MTOT / 128, 3), 256, GEMM_SMEM_BYTES>>>(
        bq, bk, bv, nullptr);

    attn_mma<<<dim3(SEQ / 64, BATCH * NH), 128, ATTN_SMEM_BYTES>>>();

    gemm_mma<3><<<dim3(DM / 128, MTOT / 128, 1), 256, GEMM_SMEM_BYTES>>>(
        bo, nullptr, nullptr, (float*)d_out);
}

// round 16
// speedup vs baseline: 1.2257x; 1.0073x over previous
#include <cuda_runtime.h>
#include <cuda_fp16.h>
#include <cstdint>
#include <cstring>

#define DM    1024
#define NH    16
#define HD    64
#define BATCH 2
#define SEQ   2048
#define MTOT  (BATCH*SEQ)   // 4096

// Scratch (allocation-free rule: __device__ globals)
__device__ __half g_qh [(long long)BATCH*NH*SEQ*HD];  // [b,h,s,hd]
__device__ __half g_kh [(long long)BATCH*NH*SEQ*HD];  // [b,h,s,hd]
__device__ __half g_vt [(long long)BATCH*NH*HD*SEQ];  // [b,h,hd,s]  (transposed!)
__device__ __half g_aoh[(long long)MTOT*DM];          // [b*s, d]
__device__ __half g_xh [(long long)MTOT*DM];          // x as fp16
__device__ __half g_WhT[(long long)4*DM*DM];          // W^T: [w][n][k]

__device__ __forceinline__ uint32_t smem_u32(const void* p) {
    uint32_t a;
    asm("{ .reg .u64 t; cvta.to.shared.u64 t, %1; cvt.u32.u64 %0, t; }"
        : "=r"(a) : "l"(p));
    return a;
}

__device__ __forceinline__ void cp16(uint32_t dst, const void* src) {
    asm volatile("cp.async.cg.shared.global [%0], [%1], 16;"
                 :: "r"(dst), "l"(src) : "memory");
}
#define CP_COMMIT() asm volatile("cp.async.commit_group;" ::: "memory")
#define CP_WAIT(n)  asm volatile("cp.async.wait_group %0;" :: "n"(n) : "memory")

__device__ __forceinline__ void mma_f16(float c[4], uint32_t a0, uint32_t a1,
                                        uint32_t a2, uint32_t a3,
                                        uint32_t b0, uint32_t b1) {
    asm volatile(
        "mma.sync.aligned.m16n8k16.row.col.f32.f16.f16.f32 "
        "{%0,%1,%2,%3}, {%4,%5,%6,%7}, {%8,%9}, {%0,%1,%2,%3};"
        : "+f"(c[0]), "+f"(c[1]), "+f"(c[2]), "+f"(c[3])
        : "r"(a0), "r"(a1), "r"(a2), "r"(a3), "r"(b0), "r"(b1));
}

__device__ __forceinline__ void ldsm_x4(uint32_t& r0, uint32_t& r1,
                                        uint32_t& r2, uint32_t& r3, uint32_t addr) {
    asm volatile("ldmatrix.sync.aligned.m8n8.x4.shared.b16 {%0,%1,%2,%3}, [%4];"
                 : "=r"(r0), "=r"(r1), "=r"(r2), "=r"(r3) : "r"(addr));
}

__device__ __forceinline__ float ex2f(float x) {
    float r;
    asm("ex2.approx.f32 %0, %1;" : "=f"(r) : "f"(x));
    return r;
}

__device__ __forceinline__ uint32_t pack_half2(float lo, float hi) {
    __half2 h = __floats2half2_rn(lo, hi);
    uint32_t u;
    memcpy(&u, &h, 4);
    return u;
}

// ===========================================================================
// Prep 1: x -> fp16.   Prep 2: W -> fp16 transposed [n][k].
// ===========================================================================
__global__ void __launch_bounds__(256)
prep_x(const float* __restrict__ x)
{
    const int i = blockIdx.x * blockDim.x + threadIdx.x;
    float4 v = ((const float4*)x)[i];
    ((__half2*)g_xh)[i * 2 + 0] = __floats2half2_rn(v.x, v.y);
    ((__half2*)g_xh)[i * 2 + 1] = __floats2half2_rn(v.z, v.w);
}

__global__ void __launch_bounds__(256)
prep_wt(const float* __restrict__ wq, const float* __restrict__ wk,
        const float* __restrict__ wv, const float* __restrict__ wo)
{
    __shared__ float s[32][33];
    const int w = blockIdx.z;
    const float* W = (w == 0) ? wq : (w == 1) ? wk : (w == 2) ? wv : wo;
    const int n0 = blockIdx.x * 32, k0 = blockIdx.y * 32;
    const int tx = threadIdx.x & 31, ty = threadIdx.x >> 5;   // 32 x 8
    #pragma unroll
    for (int r = 0; r < 4; r++)
        s[ty + r * 8][tx] = W[(size_t)(k0 + ty + r * 8) * DM + n0 + tx];
    __syncthreads();
    #pragma unroll
    for (int r = 0; r < 4; r++)
        g_WhT[(size_t)w * DM * DM + (size_t)(n0 + ty + r * 8) * DM + k0 + tx] =
            __float2half_rn(s[tx][ty + r * 8]);
}

// ===========================================================================
// FP16 mma.sync GEMM (unchanged from R15 — passing)
// ===========================================================================
#define APITCH 56
#define ATILEH (128*APITCH)
#define BUFH   (2*ATILEH)
#define NSTAGE 3
#define GEMM_SMEM_BYTES (NSTAGE*BUFH*2)   // 86016
#define NKT (DM/32)

template<int MODE>
__global__ void __launch_bounds__(256, 2)
gemm_mma(const float* __restrict__ b0,
         const float* __restrict__ b1,
         const float* __restrict__ b2,
         float* __restrict__ Cout)
{
    extern __shared__ __half smh[];
    const uint32_t sb = smem_u32(smh);

    const int t   = threadIdx.x;
    const int wid = t >> 5, lane = t & 31;
    const int grp = lane >> 2, qid = lane & 3;
    const int wr  = wid & 1, wc = wid >> 1;
    const int bn  = blockIdx.x * 128, bm = blockIdx.y * 128;
    const int z   = (MODE == 3) ? 3 : blockIdx.z;

    const __half* Ap = (MODE == 3) ? g_aoh : g_xh;
    const __half* Wt = g_WhT + (size_t)z * DM * DM;
    const float* bias = (MODE == 3) ? b0 : (z == 0) ? b0 : (z == 1) ? b1 : b2;

    // lane-invariant ldmatrix offsets (bytes)
    const int lm = lane >> 3, lr = lane & 7;
    const uint32_t aoff2 = (uint32_t)((((lm & 1) * 8 + lr) * APITCH + (lm >> 1) * 8) * 2);
    const uint32_t boff2 = (uint32_t)((((lm >> 1) * 8 + lr) * APITCH + (lm & 1) * 8) * 2);

    float c[4][4][4];
    #pragma unroll
    for (int mt = 0; mt < 4; mt++)
        #pragma unroll
        for (int nt = 0; nt < 4; nt++)
            #pragma unroll
            for (int i = 0; i < 4; i++) c[mt][nt][i] = 0.f;

    auto loadA = [&](int p, int kt) {
        #pragma unroll
        for (int i = 0; i < 2; i++) {
            int idx = t + 256 * i;
            int row = idx >> 2, c4 = idx & 3;
            cp16(sb + (uint32_t)(p * BUFH + row * APITCH + c4 * 8) * 2,
                 &Ap[(size_t)(bm + row) * DM + kt * 32 + c4 * 8]);
        }
    };
    auto loadW = [&](int p, int kt) {
        #pragma unroll
        for (int i = 0; i < 2; i++) {
            int idx = t + 256 * i;
            int row = idx >> 2, c4 = idx & 3;
            cp16(sb + (uint32_t)(p * BUFH + ATILEH + row * APITCH + c4 * 8) * 2,
                 &Wt[(size_t)(bn + row) * DM + kt * 32 + c4 * 8]);
        }
    };

    loadA(0, 0); loadW(0, 0); CP_COMMIT();
    loadA(1, 1); loadW(1, 1); CP_COMMIT();

    int cs = 0, ls = 2;
    for (int kt = 0; kt < NKT; kt++) {
        if (kt + 1 < NKT) { CP_WAIT(1); } else { CP_WAIT(0); }
        __syncthreads();

        if (kt + 2 < NKT) {
            loadA(ls, kt + 2); loadW(ls, kt + 2); CP_COMMIT();
            ls = (ls + 1 == NSTAGE) ? 0 : ls + 1;
        }

        const uint32_t As_b = sb + (uint32_t)(cs * BUFH) * 2;
        const uint32_t Ws_b = As_b + (uint32_t)ATILEH * 2;
        #pragma unroll
        for (int ks = 0; ks < 2; ks++) {
            const int kh = ks * 16;
            uint32_t af[4][4];
            #pragma unroll
            for (int mt = 0; mt < 4; mt++)
                ldsm_x4(af[mt][0], af[mt][1], af[mt][2], af[mt][3],
                        As_b + (uint32_t)(((wr * 64 + mt * 16) * APITCH + kh) * 2) + aoff2);
            uint32_t bf[4][2];
            #pragma unroll
            for (int ntb = 0; ntb < 4; ntb += 2)
                ldsm_x4(bf[ntb][0], bf[ntb][1], bf[ntb + 1][0], bf[ntb + 1][1],
                        Ws_b + (uint32_t)(((wc * 32 + ntb * 8) * APITCH + kh) * 2) + boff2);
            #pragma unroll
            for (int mt = 0; mt < 4; mt++)
                #pragma unroll
                for (int nt = 0; nt < 4; nt++)
                    mma_f16(c[mt][nt], af[mt][0], af[mt][1], af[mt][2], af[mt][3],
                            bf[nt][0], bf[nt][1]);
        }
        cs = (cs + 1 == NSTAGE) ? 0 : cs + 1;
    }

    #pragma unroll
    for (int mt = 0; mt < 4; mt++) {
        #pragma unroll
        for (int nt = 0; nt < 4; nt++) {
            const int gc = bn + wc * 32 + nt * 8 + 2 * qid;
            const float bx = bias[gc], by = bias[gc + 1];
            #pragma unroll
            for (int half = 0; half < 2; half++) {
                const int gr = bm + wr * 64 + mt * 16 + grp + half * 8;
                const float vx = c[mt][nt][half * 2 + 0] + bx;
                const float vy = c[mt][nt][half * 2 + 1] + by;
                if (MODE == 3) {
                    float2 v; v.x = vx; v.y = vy;
                    *(float2*)&Cout[(size_t)gr * DM + gc] = v;
                } else {
                    const int b = gr >> 11, s = gr & (SEQ - 1);
                    const int h = gc >> 6,  hd = gc & (HD - 1);
                    if (z == 0) {
                        *(__half2*)&g_qh[((size_t)((b * NH + h) * SEQ + s)) * HD + hd] =
                            __floats2half2_rn(vx, vy);
                    } else if (z == 1) {
                        *(__half2*)&g_kh[((size_t)((b * NH + h) * SEQ + s)) * HD + hd] =
                            __floats2half2_rn(vx, vy);
                    } else {
                        __half* vtp = g_vt + ((size_t)(b * NH + h) * HD) * SEQ;
                        vtp[(size_t)(hd + 0) * SEQ + s] = __float2half_rn(vx);
                        vtp[(size_t)(hd + 1) * SEQ + s] = __float2half_rn(vy);
                    }
                }
            }
        }
    }
}

// ===========================================================================
// FP16 mma.sync flash attention.  BQ=BK=64, 128 threads = 4 warps.
// XOR-swizzled (pad-free) smem: 64x64-half tiles, 128 B rows,
// chunk' = chunk ^ (row & 7).  P in registers; ldmatrix loads; one barrier
// per k-tile; 2-stage cp.async K/V(transposed).
// grid: (SEQ/64, BATCH*NH), reversed qt.
// ===========================================================================
#define TROW  64                       // halves per row (128 B)
#define QTILE (64*TROW)                // 4096 halves
#define SMQ   0
#define SMKV  QTILE                    // 4096
#define KVH   (2*QTILE)                // 8192 halves per stage (K + Vt)
#define ATTN_H (SMKV + 2*KVH)          // 20480 halves
#define ATTN_SMEM_BYTES (ATTN_H*2)     // 40960

__global__ void __launch_bounds__(128, 5)
attn_mma()
{
    extern __shared__ __half smh[];
    const uint32_t sb = smem_u32(smh);

    const int t    = threadIdx.x;
    const int wid  = t >> 5, lane = t & 31;
    const int grp  = lane >> 2, qid = lane & 3;
    const int qt   = gridDim.x - 1 - blockIdx.x;
    const int bh   = blockIdx.y;
    const int q0   = qt * 64;

    const __half* Qg  = g_qh + ((size_t)bh * SEQ + q0) * HD;
    const __half* Kg  = g_kh + (size_t)bh * SEQ * HD;
    const __half* Vtg = g_vt + (size_t)bh * HD * SEQ;

    // per-lane ldmatrix bases (swizzled layout, 128 B rows)
    const int lm = lane >> 3, lr = lane & 7;
    // A-type (Q): row_a = wid*16 + (lm&1)*8 + lr, chunk base = lm>>1
    const uint32_t q_row_b = (uint32_t)((wid * 16 + (lm & 1) * 8 + lr) * 128);
    const int q_cb = lm >> 1;
    // B-type (K/V): row_b = (lm>>1)*8 + lr (+ ntb*8), chunk base = lm&1
    const uint32_t b_row_b = (uint32_t)(((lm >> 1) * 8 + lr) * 128);
    const int b_cb = lm & 1;

    auto loadKV = [&](int p, int kt) {
        const int k0 = kt * 64;
        const uint32_t kb = sb + (uint32_t)(SMKV + p * KVH) * 2;
        #pragma unroll
        for (int i = 0; i < 4; i++) {
            int idx = t + 128 * i;
            int row = idx >> 3, c8 = idx & 7;       // K: 64 rows x 8 chunks
            cp16(kb + (uint32_t)(row * TROW + ((c8 ^ (row & 7)) * 8)) * 2,
                 &Kg[(size_t)(k0 + row) * HD + c8 * 8]);
        }
        #pragma unroll
        for (int i = 0; i < 4; i++) {
            int idx = t + 128 * i;
            int d = idx >> 3, c8 = idx & 7;         // Vt: 64 d-rows x 8 s-chunks
            cp16(kb + (uint32_t)(QTILE + d * TROW + ((c8 ^ (d & 7)) * 8)) * 2,
                 &Vtg[(size_t)d * SEQ + k0 + c8 * 8]);
        }
    };

    // Q tile + first K/V stage in one group
    #pragma unroll
    for (int i = 0; i < 4; i++) {
        int idx = t + 128 * i;
        int row = idx >> 3, c8 = idx & 7;
        cp16(sb + (uint32_t)(SMQ + row * TROW + ((c8 ^ (row & 7)) * 8)) * 2,
             &Qg[(size_t)row * HD + c8 * 8]);
    }
    loadKV(0, 0);
    CP_COMMIT();

    float o[8][4];
    #pragma unroll
    for (int nt = 0; nt < 8; nt++)
        #pragma unroll
        for (int i = 0; i < 4; i++) o[nt][i] = 0.f;
    float m0 = -1e30f, m1 = -1e30f, l0 = 0.f, l1 = 0.f;

    const float CE = 0.125f * 1.44269504f;   // scale * log2(e)

    const int ntiles = qt + 1;
    for (int kt = 0; kt < ntiles; kt++) {
        const int p = kt & 1;
        CP_WAIT(0);
        __syncthreads();   // stage p visible; all warps done reading stage p^1
        if (kt + 1 < ntiles) { loadKV(p ^ 1, kt + 1); CP_COMMIT(); }

        const int k0 = kt * 64;
        const uint32_t Ks_b = sb + (uint32_t)(SMKV + p * KVH) * 2;
        const uint32_t Vs_b = Ks_b + (uint32_t)QTILE * 2;
        const uint32_t Qs_b = sb;   // q_row_b already includes wid*16

        // ---- S = Q @ K^T (raw, unscaled) ----
        float s[8][4];
        #pragma unroll
        for (int nt = 0; nt < 8; nt++)
            #pragma unroll
            for (int i = 0; i < 4; i++) s[nt][i] = 0.f;

        #pragma unroll
        for (int ks = 0; ks < 4; ks++) {
            uint32_t a0, a1, a2, a3;
            ldsm_x4(a0, a1, a2, a3,
                    Qs_b + q_row_b + (uint32_t)((((ks * 2 + q_cb) ^ lr) & 7) << 4));
            const uint32_t bsw = (uint32_t)((((ks * 2 + b_cb) ^ lr) & 7) << 4);
            #pragma unroll
            for (int ntb = 0; ntb < 8; ntb += 2) {
                uint32_t b0, b1, b2, b3;
                ldsm_x4(b0, b1, b2, b3, Ks_b + (uint32_t)(ntb * 1024) + b_row_b + bsw);
                mma_f16(s[ntb],     a0, a1, a2, a3, b0, b1);
                mma_f16(s[ntb + 1], a0, a1, a2, a3, b2, b3);
            }
        }

        // ---- causal mask (diagonal tile only) + row max on raw S ----
        const int r_lo = q0 + wid * 16 + grp;
        const int r_hi = r_lo + 8;
        float lm0 = -1e30f, lm1 = -1e30f;
        const bool domask = (kt == ntiles - 1);
        #pragma unroll
        for (int nt = 0; nt < 8; nt++) {
            const int cg = k0 + nt * 8 + 2 * qid;
            if (domask) {
                if (cg     > r_lo) s[nt][0] = -1e30f;
                if (cg + 1 > r_lo) s[nt][1] = -1e30f;
                if (cg     > r_hi) s[nt][2] = -1e30f;
                if (cg + 1 > r_hi) s[nt][3] = -1e30f;
            }
            lm0 = fmaxf(lm0, fmaxf(s[nt][0], s[nt][1]));
            lm1 = fmaxf(lm1, fmaxf(s[nt][2], s[nt][3]));
        }
        lm0 = fmaxf(lm0, __shfl_xor_sync(0xFFFFFFFFu, lm0, 1));
        lm0 = fmaxf(lm0, __shfl_xor_sync(0xFFFFFFFFu, lm0, 2));
        lm1 = fmaxf(lm1, __shfl_xor_sync(0xFFFFFFFFu, lm1, 1));
        lm1 = fmaxf(lm1, __shfl_xor_sync(0xFFFFFFFFu, lm1, 2));

        const float mn0 = fmaxf(m0, lm0), mn1 = fmaxf(m1, lm1);
        const float mc0 = mn0 * CE, mc1 = mn1 * CE;
        const float corr0 = ex2f(fmaf(m0, CE, -mc0));
        const float corr1 = ex2f(fmaf(m1, CE, -mc1));
        m0 = mn0; m1 = mn1;

        // ---- exp + row sums + P fragments IN REGISTERS ----
        float ls0 = 0.f, ls1 = 0.f;
        uint32_t pp[8][2];
        #pragma unroll
        for (int nt = 0; nt < 8; nt++) {
            float p0 = ex2f(fmaf(s[nt][0], CE, -mc0));
            float p1 = ex2f(fmaf(s[nt][1], CE, -mc0));
            float p2 = ex2f(fmaf(s[nt][2], CE, -mc1));
            float p3 = ex2f(fmaf(s[nt][3], CE, -mc1));
            ls0 += p0 + p1; ls1 += p2 + p3;
            pp[nt][0] = pack_half2(p0, p1);
            pp[nt][1] = pack_half2(p2, p3);
        }
        ls0 += __shfl_xor_sync(0xFFFFFFFFu, ls0, 1);
        ls0 += __shfl_xor_sync(0xFFFFFFFFu, ls0, 2);
        ls1 += __shfl_xor_sync(0xFFFFFFFFu, ls1, 1);
        ls1 += __shfl_xor_sync(0xFFFFFFFFu, ls1, 2);
        l0 = l0 * corr0 + ls0;
        l1 = l1 * corr1 + ls1;

        #pragma unroll
        for (int nt = 0; nt < 8; nt++) {
            o[nt][0] *= corr0; o[nt][1] *= corr0;
            o[nt][2] *= corr1; o[nt][3] *= corr1;
        }

        // ---- O += P @ V : A-fragments from pp, B via swizzled ldmatrix ----
        #pragma unroll
        for (int ks = 0; ks < 4; ks++) {
            uint32_t a0 = pp[2 * ks][0];
            uint32_t a1 = pp[2 * ks][1];
            uint32_t a2 = pp[2 * ks + 1][0];
            uint32_t a3 = pp[2 * ks + 1][1];
            const uint32_t bsw = (uint32_t)((((ks * 2 + b_cb) ^ lr) & 7) << 4);
            #pragma unroll
            for (int ntb = 0; ntb < 8; ntb += 2) {
                uint32_t b0, b1, b2, b3;
                ldsm_x4(b0, b1, b2, b3, Vs_b + (uint32_t)(ntb * 1024) + b_row_b + bsw);
                mma_f16(o[ntb],     a0, a1, a2, a3, b0, b1);
                mma_f16(o[ntb + 1], a0, a1, a2, a3, b2, b3);
            }
        }
        // no end-of-loop barrier: next iteration's top barrier protects reuse
    }

    // ---- epilogue: normalize, fp16-round, scatter to g_aoh [b*s, d] ----
    const int b = bh >> 4, h = bh & (NH - 1);
    const float inv0 = 1.f / l0, inv1 = 1.f / l1;
    const int s_lo = q0 + wid * 16 + grp;
    const int s_hi = s_lo + 8;
    #pragma unroll
    for (int nt = 0; nt < 8; nt++) {
        const int col = h * HD + nt * 8 + 2 * qid;
        *(__half2*)&g_aoh[((size_t)(b * SEQ + s_lo)) * DM + col] =
            __floats2half2_rn(o[nt][0] * inv0, o[nt][1] * inv0);
        *(__half2*)&g_aoh[((size_t)(b * SEQ + s_hi)) * DM + col] =
            __floats2half2_rn(o[nt][2] * inv1, o[nt][3] * inv1);
    }
}

// ---------------------------------------------------------------------------
extern "C" void kernel_launch(void* const* d_in, const int* in_sizes, int n_in,
                              void* d_out, int out_size)
{
    const float* x  = (const float*)d_in[0];
    const float* Wq = (const float*)d_in[1];
    const float* bq = (const float*)d_in[2];
    const float* Wk = (const float*)d_in[3];
    const float* bk = (const float*)d_in[4];
    const float* Wv = (const float*)d_in[5];
    const float* bv = (const float*)d_in[6];
    const float* Wo = (const float*)d_in[7];
    const float* bo = (const float*)d_in[8];

    cudaFuncSetAttribute(gemm_mma<0>,
                         cudaFuncAttributeMaxDynamicSharedMemorySize, GEMM_SMEM_BYTES);
    cudaFuncSetAttribute(gemm_mma<3>,
                         cudaFuncAttributeMaxDynamicSharedMemorySize, GEMM_SMEM_BYTES);
    cudaFuncSetAttribute(attn_mma,
                         cudaFuncAttributeMaxDynamicSharedMemorySize, ATTN_SMEM_BYTES);

    prep_x<<<MTOT * DM / 4 / 256, 256>>>(x);
    prep_wt<<<dim3(DM / 32, DM / 32, 4), 256>>>(Wq, Wk, Wv, Wo);

    gemm_mma<0><<<dim3(DM / 128, MTOT / 128, 3), 256, GEMM_SMEM_BYTES>>>(
        bq, bk, bv, nullptr);

    attn_mma<<<dim3(SEQ / 64, BATCH * NH), 128, ATTN_SMEM_BYTES>>>();

    gemm_mma<3><<<dim3(DM / 128, MTOT / 128, 1), 256, GEMM_SMEM_BYTES>>>(
        bo, nullptr, nullptr, (float*)d_out);
}